// round 13
// baseline (speedup 1.0000x reference)
#include <cuda_runtime.h>
#include <cuda_bf16.h>
#include <stdint.h>
#include <math.h>

// Problem constants
#define CIN   256
#define COUT  128
#define KK    9
#define HIN   64
#define WIN   64
#define XP    65          // padded x dims (extra zero row/col)
#define HH    128
#define WW    128
#define NB    2
#define KTOT  (KK * COUT)        // 1152
#define STAGES (KTOT / 32)       // 36

// ---------------- device scratch (no allocations allowed) ----------------
__device__ __align__(16) float g_upcl[NB * HH * WW * COUT]; // up fp32, channel-last (16MB)
__device__ int   g_sy[NB][KK], g_sx[NB][KK];
__device__ float g_cw[NB][KK][4];
__device__ __align__(16) __nv_bfloat16 g_Whi[CIN * KTOT];   // deform W [o][kk*128+ci]
__device__ __align__(16) __nv_bfloat16 g_Wlo[CIN * KTOT];
__device__ __align__(16) __nv_bfloat16 g_xpad_hi[NB * XP * XP * CIN]; // 4.3MB
__device__ __align__(16) __nv_bfloat16 g_xpad_lo[NB * XP * XP * CIN];
__device__ __align__(16) __nv_bfloat16 g_Wch[COUT * 2304];  // tconv class weights
__device__ __align__(16) __nv_bfloat16 g_Wcl[COUT * 2304];

__constant__ int c_clsBase[4] = {0, 256, 768, 1280};
__constant__ int c_clsK[4]    = {256, 512, 512, 1024};

// ---------------- PTX helpers (target-independent, sm_80+) ----------------
__device__ __forceinline__ uint32_t s2u(const void* p) {
    uint32_t a;
    asm("{ .reg .u64 t; cvta.to.shared.u64 t, %1; cvt.u32.u64 %0, t; }" : "=r"(a) : "l"(p));
    return a;
}
__device__ __forceinline__ void cp16(uint32_t d, const void* s) {
    asm volatile("cp.async.cg.shared.global [%0], [%1], 16;" :: "r"(d), "l"(s));
}
__device__ __forceinline__ void cp_commit() {
    asm volatile("cp.async.commit_group;" ::: "memory");
}
__device__ __forceinline__ void cp_wait_all() {
    asm volatile("cp.async.wait_group 0;" ::: "memory");
}
__device__ __forceinline__ void ldsm4(uint32_t* r, uint32_t a) {
    asm volatile("ldmatrix.sync.aligned.m8n8.x4.shared.b16 {%0,%1,%2,%3}, [%4];"
                 : "=r"(r[0]), "=r"(r[1]), "=r"(r[2]), "=r"(r[3]) : "r"(a));
}
__device__ __forceinline__ void ldsm2(uint32_t* r, uint32_t a) {
    asm volatile("ldmatrix.sync.aligned.m8n8.x2.shared.b16 {%0,%1}, [%2];"
                 : "=r"(r[0]), "=r"(r[1]) : "r"(a));
}
__device__ __forceinline__ void mma_bf16(float* d, const uint32_t* a, const uint32_t* b) {
    asm volatile(
        "mma.sync.aligned.m16n8k16.row.col.f32.bf16.bf16.f32 "
        "{%0,%1,%2,%3}, {%4,%5,%6,%7}, {%8,%9}, {%0,%1,%2,%3};"
        : "+f"(d[0]), "+f"(d[1]), "+f"(d[2]), "+f"(d[3])
        : "r"(a[0]), "r"(a[1]), "r"(a[2]), "r"(a[3]), "r"(b[0]), "r"(b[1]));
}

union BFP { __nv_bfloat16 b[4]; uint2 v; };
union BF8U { __nv_bfloat16 b[8]; uint4 v; };

// ---------------------------------------------------------------------------
// Kernel 1: fused weight preprocessing (deform split + tconv class weights)
// ---------------------------------------------------------------------------
__global__ void wprep_kernel(const float* __restrict__ tw) {
    int i = blockIdx.x * blockDim.x + threadIdx.x;
    if (i >= CIN * KTOT) return;
    {   // deform split
        int o = i / KTOT, kidx = i % KTOT;
        int kk = kidx >> 7, ci = kidx & 127;
        float w = tw[(o * COUT + ci) * KK + kk];
        __nv_bfloat16 h = __float2bfloat16(w);
        g_Whi[i] = h;
        g_Wlo[i] = __float2bfloat16(w - __bfloat162float(h));
    }
    {   // tconv class weights
        int co = i / 2304, kf = i % 2304;
        int cls = (kf >= 1280) ? 3 : (kf >= 768) ? 2 : (kf >= 256) ? 1 : 0;
        int k = kf - c_clsBase[cls];
        int py = cls >> 1, pxp = cls & 1;
        int nkx = pxp ? 2 : 1;
        int tap = k >> 8, ci = k & 255;
        int a = tap / nkx, b = tap % nkx;
        int ky = py ? (a ? 2 : 0) : 1;
        int kx = pxp ? (b ? 2 : 0) : 1;
        float w = tw[(ci * COUT + co) * KK + (2 - ky) * 3 + (2 - kx)];
        __nv_bfloat16 h = __float2bfloat16(w);
        g_Wch[i] = h;
        g_Wcl[i] = __float2bfloat16(w - __bfloat162float(h));
    }
}

// ---------------------------------------------------------------------------
// Kernel 2: x -> channel-last bf16 hi/lo with zero pad row/col 64.
// ---------------------------------------------------------------------------
__global__ void __launch_bounds__(256)
xsplit_kernel(const float* __restrict__ x) {
    const int y0 = blockIdx.x, n = blockIdx.y;
    const int tid = threadIdx.x;
    __nv_bfloat16* oh = g_xpad_hi + (size_t)(n * XP + y0) * XP * CIN;
    __nv_bfloat16* ol = g_xpad_lo + (size_t)(n * XP + y0) * XP * CIN;

    if (y0 == 64) {
        for (int idx = tid; idx < XP * CIN / 8; idx += 256) {
            *(uint4*)(oh + idx * 8) = make_uint4(0, 0, 0, 0);
            *(uint4*)(ol + idx * 8) = make_uint4(0, 0, 0, 0);
        }
        return;
    }
    __shared__ float tile[64][65];
    for (int cc = 0; cc < 4; cc++) {
        #pragma unroll
        for (int r = 0; r < 16; r++) {
            int ci = (tid >> 6) + r * 4;
            int x0 = tid & 63;
            tile[ci][x0] = x[((size_t)(n * CIN + cc * 64 + ci) * HIN + y0) * WIN + x0];
        }
        __syncthreads();
        #pragma unroll
        for (int r = 0; r < 16; r++) {
            int x0 = (tid >> 6) + r * 4;
            int ci = tid & 63;
            float v = tile[ci][x0];
            __nv_bfloat16 h = __float2bfloat16(v);
            oh[x0 * CIN + cc * 64 + ci] = h;
            ol[x0 * CIN + cc * 64 + ci] = __float2bfloat16(v - __bfloat162float(h));
        }
        __syncthreads();
    }
    if (tid < CIN) {
        oh[64 * CIN + tid] = __float2bfloat16(0.f);
        ol[64 * CIN + tid] = __float2bfloat16(0.f);
    }
}

// ---------------------------------------------------------------------------
// Kernel 3: offset branch, warp-parallel
// ---------------------------------------------------------------------------
__global__ void __launch_bounds__(1024)
offsets_kernel(const float* __restrict__ lat,
               const float* __restrict__ w1,
               const float* __restrict__ b1,
               const float* __restrict__ w2,
               const float* __restrict__ b2) {
    __shared__ float h[NB][64];
    __shared__ float oc[NB][18];
    const int tid = threadIdx.x, lane = tid & 31, w = tid >> 5;

    #pragma unroll
    for (int t = 0; t < 4; t++) {
        int o = w * 4 + t;
        int n = o >> 6, j = o & 63;
        float s = 0.f;
        #pragma unroll
        for (int r = 0; r < 4; r++) {
            int i = lane + r * 32;
            s += lat[n * COUT + i] * w1[(j * COUT + i) * KK + 4];
        }
        #pragma unroll
        for (int d = 16; d; d >>= 1) s += __shfl_xor_sync(0xffffffffu, s, d);
        if (lane == 0) h[n][j] = fmaxf(s + b1[j], 0.f);
    }
    __syncthreads();

    for (int o = w; o < NB * 18; o += 32) {
        int n = o / 18, c = o % 18;
        float s = 0.f;
        #pragma unroll
        for (int r = 0; r < 2; r++) {
            int k = lane + r * 32;
            s += h[n][k] * w2[(c * 64 + k) * KK + 4];
        }
        #pragma unroll
        for (int d = 16; d; d >>= 1) s += __shfl_xor_sync(0xffffffffu, s, d);
        if (lane == 0) oc[n][c] = tanhf(s + b2[c]);
    }
    __syncthreads();

    if (tid < NB * KK) {
        int n = tid / KK, kk = tid % KK;
        float oy = oc[n][2 * kk], ox = oc[n][2 * kk + 1];
        float fy = floorf(oy), fx = floorf(ox);
        float dy = oy - fy,  dx = ox - fx;
        g_sy[n][kk] = (kk / 3 - 1) + (int)fy;
        g_sx[n][kk] = (kk % 3 - 1) + (int)fx;
        g_cw[n][kk][0] = (1.f - dy) * (1.f - dx);
        g_cw[n][kk][1] = (1.f - dy) * dx;
        g_cw[n][kk][2] = dy * (1.f - dx);
        g_cw[n][kk][3] = dy * dx;
    }
}

// ---------------------------------------------------------------------------
// Kernel 4: transposed conv as per-parity-class HMMA GEMM (unchanged R6)
// ---------------------------------------------------------------------------
__global__ void __launch_bounds__(256, 1)
tconv_gemm_kernel() {
    extern __shared__ __align__(16) unsigned char smraw[];
    const int Y   = blockIdx.x;
    const int pxp = blockIdx.y;
    const int n   = blockIdx.z;
    const int tid = threadIdx.x;
    const int lane = tid & 31, warp = tid >> 5;
    const int wm = warp & 1, wn = warp >> 1;

    const int py  = Y & 1;
    const int cls = py * 2 + pxp;
    const int Kc  = c_clsK[cls];
    const int kbase = c_clsBase[cls];
    const int nkx = pxp ? 2 : 1;
    const int stages = Kc >> 5;
    const int y0b = Y >> 1;
    const uint32_t smb = s2u(smraw);

    const __nv_bfloat16* Ah_src = g_Wch;
    const __nv_bfloat16* Al_src = g_Wcl;
    const __nv_bfloat16* Bh_src = g_xpad_hi + (size_t)n * XP * XP * CIN;
    const __nv_bfloat16* Bl_src = g_xpad_lo + (size_t)n * XP * XP * CIN;

    float acc[4][2][4];
    #pragma unroll
    for (int i = 0; i < 4; i++)
        #pragma unroll
        for (int j = 0; j < 2; j++)
            #pragma unroll
            for (int e = 0; e < 4; e++) acc[i][j][e] = 0.f;

    auto issue = [&](int s, int buf) {
        const int k0 = s * 32;
        const int tap = k0 >> 8;
        const int a = tap / nkx, b = tap % nkx;
        const int yy = y0b + (py ? a : 0);
        const int d  = pxp ? b : 0;
        const int cib = k0 & 255;
        const size_t brow = ((size_t)yy * XP) * CIN;
        #pragma unroll
        for (int j = 0; j < 6; j++) {
            int id = tid + j * 256;
            uint32_t base = smb + buf * 30720;
            if (id < 1024) {
                int t = id >> 9;
                int rid = id & 511;
                int r = rid >> 2, c = rid & 3;
                uint32_t dst = base + t * 10240 + r * 80 + c * 16;
                const __nv_bfloat16* src = (t ? Al_src : Ah_src)
                    + (size_t)r * 2304 + kbase + k0 + c * 8;
                cp16(dst, src);
            } else {
                int rid = id - 1024;
                int t = rid >> 8;
                int rr = rid & 255;
                int r = rr >> 2, c = rr & 3;
                uint32_t dst = base + 20480 + t * 5120 + r * 80 + c * 16;
                const __nv_bfloat16* src = (t ? Bl_src : Bh_src)
                    + brow + (size_t)(r + d) * CIN + cib + c * 8;
                cp16(dst, src);
            }
        }
        cp_commit();
    };

    issue(0, 0);

    for (int s = 0; s < stages; s++) {
        cp_wait_all();
        __syncthreads();
        if (s + 1 < stages) issue(s + 1, (s + 1) & 1);

        const int buf = s & 1;
        const uint32_t Ab = smb + buf * 30720;
        const uint32_t Bb = Ab + 20480;

        #pragma unroll
        for (int ks = 0; ks < 2; ks++) {
            uint32_t afr[2][4][4];
            #pragma unroll
            for (int t = 0; t < 2; t++)
                #pragma unroll
                for (int mt = 0; mt < 4; mt++) {
                    uint32_t ad = Ab + t * 10240 +
                        (wm * 64 + mt * 16 + (lane & 15)) * 80 + ks * 32 + (lane >> 4) * 16;
                    ldsm4(afr[t][mt], ad);
                }
            uint32_t bfr[2][2][2];
            #pragma unroll
            for (int t = 0; t < 2; t++)
                #pragma unroll
                for (int nt = 0; nt < 2; nt++) {
                    uint32_t bd = Bb + t * 5120 +
                        (wn * 16 + nt * 8 + (lane & 7)) * 80 + ks * 32 + ((lane >> 3) & 1) * 16;
                    ldsm2(bfr[t][nt], bd);
                }
            #pragma unroll
            for (int mt = 0; mt < 4; mt++)
                #pragma unroll
                for (int nt = 0; nt < 2; nt++) {
                    mma_bf16(acc[mt][nt], afr[0][mt], bfr[0][nt]);
                    mma_bf16(acc[mt][nt], afr[0][mt], bfr[1][nt]);
                    mma_bf16(acc[mt][nt], afr[1][mt], bfr[0][nt]);
                }
        }
        __syncthreads();
    }

    float* up = g_upcl + (size_t)(n * HH + Y) * WW * COUT;
    #pragma unroll
    for (int mt = 0; mt < 4; mt++) {
        int m0 = wm * 64 + mt * 16 + (lane >> 2);
        #pragma unroll
        for (int nt = 0; nt < 2; nt++) {
            int px0 = wn * 16 + nt * 8 + (lane & 3) * 2;
            up[(size_t)(2 * px0 + pxp) * COUT + m0]           = acc[mt][nt][0];
            up[(size_t)(2 * (px0 + 1) + pxp) * COUT + m0]     = acc[mt][nt][1];
            up[(size_t)(2 * px0 + pxp) * COUT + m0 + 8]       = acc[mt][nt][2];
            up[(size_t)(2 * (px0 + 1) + pxp) * COUT + m0 + 8] = acc[mt][nt][3];
        }
    }
}

// ---------------------------------------------------------------------------
// Kernel 5: FUSED deform GEMM: B tiles sampled on the fly from g_upcl (L2),
// blended fp32 -> bf16 hi/lo, double-buffered; A via cp.async.
// Grid (y, ob, n). CTA: M=128 o x N=128 px, K=1152.
// smem/buf: Ah 10240 | Al 10240 | Bh 10240 | Bl 10240 = 40960; x2 = 81920.
// ---------------------------------------------------------------------------
__global__ void __launch_bounds__(256, 1)
gemm_kernel(float* __restrict__ out) {
    extern __shared__ __align__(16) unsigned char smraw[];
    const int y   = blockIdx.x;
    const int ob  = blockIdx.y;
    const int n   = blockIdx.z;
    const int tid = threadIdx.x;
    const int lane = tid & 31, warp = tid >> 5;
    const int wm = warp & 1, wn = warp >> 1;

    const uint32_t smb = s2u(smraw);

    __shared__ int   ssy[KK], ssx[KK];
    __shared__ float scw[KK][4];
    if (tid < KK) { ssy[tid] = g_sy[n][tid]; ssx[tid] = g_sx[n][tid]; }
    if (tid < KK * 4) ((float*)scw)[tid] = ((const float*)g_cw[n])[tid];
    __syncthreads();

    const __nv_bfloat16* srcA_h = g_Whi + (size_t)(ob * 128) * KTOT;
    const __nv_bfloat16* srcA_l = g_Wlo + (size_t)(ob * 128) * KTOT;
    const float* up_n = g_upcl + (size_t)n * HH * WW * COUT;

    // this thread's B-fill coordinates: px = tid>>1, ci half = (tid&1)*16
    const int b_px  = tid >> 1;
    const int b_cih = (tid & 1) * 16;

    float acc[4][4][4];
    #pragma unroll
    for (int i = 0; i < 4; i++)
        #pragma unroll
        for (int j = 0; j < 4; j++)
            #pragma unroll
            for (int e = 0; e < 4; e++) acc[i][j][e] = 0.f;

    // A cp.async: 2 tiles x 512 cp16 = 1024 / 256thr = 4 each
    auto issueA = [&](int s, int buf) {
        const int k0 = s * 32;
        #pragma unroll
        for (int j = 0; j < 4; j++) {
            int id = tid + j * 256;
            int t = id >> 9;
            int rid = id & 511;
            int r = rid >> 2, c = rid & 3;
            uint32_t dst = smb + buf * 40960 + t * 10240 + r * 80 + c * 16;
            const __nv_bfloat16* src = (t ? srcA_l : srcA_h) + (size_t)r * KTOT + k0 + c * 8;
            cp16(dst, src);
        }
        cp_commit();
    };

    float4 r0[4], r1[4], r2[4], r3[4];   // 4 corners x 16 ci
    float  cc0, cc1, cc2, cc3;

    // B gather: issue 16 predicated LDG.128 into regs (no blending yet)
    auto loadB = [&](int s) {
        const int kk = s >> 2;
        const int ci0 = ((s & 3) * 32) + b_cih;
        const int sy = ssy[kk], sx = ssx[kk];
        cc0 = scw[kk][0]; cc1 = scw[kk][1]; cc2 = scw[kk][2]; cc3 = scw[kk][3];
        const int yy = y + sy, xx = b_px + sx;
        const bool o00 = ((unsigned)yy < HH) & ((unsigned)xx < WW);
        const bool o01 = ((unsigned)yy < HH) & ((unsigned)(xx + 1) < WW);
        const bool o10 = ((unsigned)(yy + 1) < HH) & ((unsigned)xx < WW);
        const bool o11 = ((unsigned)(yy + 1) < HH) & ((unsigned)(xx + 1) < WW);
        const float4* p = (const float4*)(up_n + ((size_t)yy * WW + xx) * COUT + ci0);
        const float4 z = make_float4(0.f, 0.f, 0.f, 0.f);
        #pragma unroll
        for (int j = 0; j < 4; j++) {
            r0[j] = o00 ? p[j] : z;
            r1[j] = o01 ? p[j + COUT / 4] : z;
            r2[j] = o10 ? p[j + WW * COUT / 4] : z;
            r3[j] = o11 ? p[j + (WW + 1) * COUT / 4] : z;
        }
    };

    // blend + split + store to smem B buffer
    auto storeB = [&](int buf) {
        float v[16];
        #pragma unroll
        for (int j = 0; j < 4; j++) {
            v[4 * j + 0] = cc0 * r0[j].x + cc1 * r1[j].x + cc2 * r2[j].x + cc3 * r3[j].x;
            v[4 * j + 1] = cc0 * r0[j].y + cc1 * r1[j].y + cc2 * r2[j].y + cc3 * r3[j].y;
            v[4 * j + 2] = cc0 * r0[j].z + cc1 * r1[j].z + cc2 * r2[j].z + cc3 * r3[j].z;
            v[4 * j + 3] = cc0 * r0[j].w + cc1 * r1[j].w + cc2 * r2[j].w + cc3 * r3[j].w;
        }
        BF8U vh0, vh1, vl0, vl1;
        #pragma unroll
        for (int e = 0; e < 8; e++) {
            __nv_bfloat16 hb = __float2bfloat16(v[e]);
            vh0.b[e] = hb;
            vl0.b[e] = __float2bfloat16(v[e] - __bfloat162float(hb));
            __nv_bfloat16 hb2 = __float2bfloat16(v[8 + e]);
            vh1.b[e] = hb2;
            vl1.b[e] = __float2bfloat16(v[8 + e] - __bfloat162float(hb2));
        }
        uint32_t boff = buf * 40960 + 20480 + b_px * 80 + (b_cih ? 32 : 0);
        *(uint4*)(smraw + boff)         = vh0.v;
        *(uint4*)(smraw + boff + 16)    = vh1.v;
        *(uint4*)(smraw + boff + 10240)      = vl0.v;
        *(uint4*)(smraw + boff + 10240 + 16) = vl1.v;
    };

    issueA(0, 0);
    loadB(0);

    for (int s = 0; s < STAGES; s++) {
        const int buf = s & 1;
        cp_wait_all();          // A(s) landed
        storeB(buf);            // blend regs (loaded in prev iter) -> smem
        __syncthreads();
        if (s + 1 < STAGES) {
            issueA(s + 1, buf ^ 1);
            loadB(s + 1);       // LDGs land during compute below
        }

        const uint32_t Ab = smb + buf * 40960;
        const uint32_t Bb = Ab + 20480;

        #pragma unroll
        for (int ks = 0; ks < 2; ks++) {
            uint32_t afr[2][4][4];
            #pragma unroll
            for (int t = 0; t < 2; t++)
                #pragma unroll
                for (int mt = 0; mt < 4; mt++) {
                    uint32_t ad = Ab + t * 10240 +
                        (wm * 64 + mt * 16 + (lane & 15)) * 80 + ks * 32 + (lane >> 4) * 16;
                    ldsm4(afr[t][mt], ad);
                }
            uint32_t bfr[2][4][2];
            #pragma unroll
            for (int t = 0; t < 2; t++)
                #pragma unroll
                for (int nt = 0; nt < 4; nt++) {
                    uint32_t bd = Bb + t * 10240 +
                        (wn * 32 + nt * 8 + (lane & 7)) * 80 + ks * 32 + ((lane >> 3) & 1) * 16;
                    ldsm2(bfr[t][nt], bd);
                }
            #pragma unroll
            for (int mt = 0; mt < 4; mt++)
                #pragma unroll
                for (int nt = 0; nt < 4; nt++) {
                    mma_bf16(acc[mt][nt], afr[0][mt], bfr[0][nt]);
                    mma_bf16(acc[mt][nt], afr[0][mt], bfr[1][nt]);
                    mma_bf16(acc[mt][nt], afr[1][mt], bfr[0][nt]);
                }
        }
        __syncthreads();
    }

    #pragma unroll
    for (int mt = 0; mt < 4; mt++) {
        int m = wm * 64 + mt * 16 + (lane >> 2);
        float* pbase = out + (((size_t)(n * CIN + ob * 128 + m) * HH + y) * WW);
        #pragma unroll
        for (int nt = 0; nt < 4; nt++) {
            int xcol = wn * 32 + nt * 8 + (lane & 3) * 2;
            *(float2*)(pbase + xcol) = make_float2(acc[mt][nt][0], acc[mt][nt][1]);
            *(float2*)(pbase + 8 * HH * WW + xcol) = make_float2(acc[mt][nt][2], acc[mt][nt][3]);
        }
    }
}

// ---------------------------------------------------------------------------
extern "C" void kernel_launch(void* const* d_in, const int* in_sizes, int n_in,
                              void* d_out, int out_size) {
    const float* x   = (const float*)d_in[0];
    const float* lat = (const float*)d_in[1];
    const float* tw  = (const float*)d_in[2];
    const float* w1  = (const float*)d_in[3];
    const float* b1  = (const float*)d_in[4];
    const float* w2  = (const float*)d_in[5];
    const float* b2  = (const float*)d_in[6];
    float* out = (float*)d_out;

    cudaFuncSetAttribute(gemm_kernel,
                         cudaFuncAttributeMaxDynamicSharedMemorySize, 81920);
    cudaFuncSetAttribute(tconv_gemm_kernel,
                         cudaFuncAttributeMaxDynamicSharedMemorySize, 61440);

    wprep_kernel<<<(CIN * KTOT + 255) / 256, 256>>>(tw);
    xsplit_kernel<<<dim3(XP, NB), 256>>>(x);
    offsets_kernel<<<1, 1024>>>(lat, w1, b1, w2, b2);
    {
        dim3 grid(HH, 2, NB);
        tconv_gemm_kernel<<<grid, 256, 61440>>>();
    }
    {
        dim3 grid(HH, 2, NB);
        gemm_kernel<<<grid, 256, 81920>>>(out);
    }
}

// round 14
// speedup vs baseline: 1.4058x; 1.4058x over previous
#include <cuda_runtime.h>
#include <cuda_bf16.h>
#include <stdint.h>
#include <math.h>

// Problem constants
#define CIN   256
#define COUT  128
#define KK    9
#define HIN   64
#define WIN   64
#define XP    65          // padded x dims (extra zero row/col)
#define HH    128
#define WW    128
#define NB    2
#define KTOT  (KK * COUT)        // 1152
#define STAGES (KTOT / 32)       // 36

// ---------------- device scratch (no allocations allowed) ----------------
__device__ __align__(16) float g_upcl[NB * HH * WW * COUT]; // up fp32, channel-last (16MB)
__device__ int   g_sy[NB][KK], g_sx[NB][KK];
__device__ float g_cw[NB][KK][4];
__device__ __align__(16) __nv_bfloat16 g_Whi[CIN * KTOT];   // deform W [o][kk*128+ci]
__device__ __align__(16) __nv_bfloat16 g_Wlo[CIN * KTOT];
__device__ __align__(16) __nv_bfloat16 g_Shi[NB * HH * WW * KTOT]; // 75.5MB
__device__ __align__(16) __nv_bfloat16 g_Slo[NB * HH * WW * KTOT]; // 75.5MB
__device__ __align__(16) __nv_bfloat16 g_xpad_hi[NB * XP * XP * CIN]; // 4.3MB
__device__ __align__(16) __nv_bfloat16 g_xpad_lo[NB * XP * XP * CIN];
__device__ __align__(16) __nv_bfloat16 g_Wch[COUT * 2304];  // tconv class weights
__device__ __align__(16) __nv_bfloat16 g_Wcl[COUT * 2304];

__constant__ int c_clsBase[4] = {0, 256, 768, 1280};
__constant__ int c_clsK[4]    = {256, 512, 512, 1024};

// ---------------- PTX helpers (target-independent, sm_80+) ----------------
__device__ __forceinline__ uint32_t s2u(const void* p) {
    uint32_t a;
    asm("{ .reg .u64 t; cvta.to.shared.u64 t, %1; cvt.u32.u64 %0, t; }" : "=r"(a) : "l"(p));
    return a;
}
__device__ __forceinline__ void cp16(uint32_t d, const void* s) {
    asm volatile("cp.async.cg.shared.global [%0], [%1], 16;" :: "r"(d), "l"(s));
}
__device__ __forceinline__ void cp_commit() {
    asm volatile("cp.async.commit_group;" ::: "memory");
}
__device__ __forceinline__ void cp_wait_all() {
    asm volatile("cp.async.wait_group 0;" ::: "memory");
}
__device__ __forceinline__ void cp_wait_1() {
    asm volatile("cp.async.wait_group 1;" ::: "memory");
}
__device__ __forceinline__ void ldsm4(uint32_t* r, uint32_t a) {
    asm volatile("ldmatrix.sync.aligned.m8n8.x4.shared.b16 {%0,%1,%2,%3}, [%4];"
                 : "=r"(r[0]), "=r"(r[1]), "=r"(r[2]), "=r"(r[3]) : "r"(a));
}
__device__ __forceinline__ void ldsm2(uint32_t* r, uint32_t a) {
    asm volatile("ldmatrix.sync.aligned.m8n8.x2.shared.b16 {%0,%1}, [%2];"
                 : "=r"(r[0]), "=r"(r[1]) : "r"(a));
}
__device__ __forceinline__ void mma_bf16(float* d, const uint32_t* a, const uint32_t* b) {
    asm volatile(
        "mma.sync.aligned.m16n8k16.row.col.f32.bf16.bf16.f32 "
        "{%0,%1,%2,%3}, {%4,%5,%6,%7}, {%8,%9}, {%0,%1,%2,%3};"
        : "+f"(d[0]), "+f"(d[1]), "+f"(d[2]), "+f"(d[3])
        : "r"(a[0]), "r"(a[1]), "r"(a[2]), "r"(a[3]), "r"(b[0]), "r"(b[1]));
}

union BFP { __nv_bfloat16 b[4]; uint2 v; };

// ---------------------------------------------------------------------------
// Kernel 1: fused weight preprocessing (deform split + tconv class weights)
// ---------------------------------------------------------------------------
__global__ void wprep_kernel(const float* __restrict__ tw) {
    int i = blockIdx.x * blockDim.x + threadIdx.x;
    if (i >= CIN * KTOT) return;
    {   // deform split
        int o = i / KTOT, kidx = i % KTOT;
        int kk = kidx >> 7, ci = kidx & 127;
        float w = tw[(o * COUT + ci) * KK + kk];
        __nv_bfloat16 h = __float2bfloat16(w);
        g_Whi[i] = h;
        g_Wlo[i] = __float2bfloat16(w - __bfloat162float(h));
    }
    {   // tconv class weights
        int co = i / 2304, kf = i % 2304;
        int cls = (kf >= 1280) ? 3 : (kf >= 768) ? 2 : (kf >= 256) ? 1 : 0;
        int k = kf - c_clsBase[cls];
        int py = cls >> 1, pxp = cls & 1;
        int nkx = pxp ? 2 : 1;
        int tap = k >> 8, ci = k & 255;
        int a = tap / nkx, b = tap % nkx;
        int ky = py ? (a ? 2 : 0) : 1;
        int kx = pxp ? (b ? 2 : 0) : 1;
        float w = tw[(ci * COUT + co) * KK + (2 - ky) * 3 + (2 - kx)];
        __nv_bfloat16 h = __float2bfloat16(w);
        g_Wch[i] = h;
        g_Wcl[i] = __float2bfloat16(w - __bfloat162float(h));
    }
}

// ---------------------------------------------------------------------------
// Kernel 2: x -> channel-last bf16 hi/lo with zero pad row/col 64.
// ---------------------------------------------------------------------------
__global__ void __launch_bounds__(256)
xsplit_kernel(const float* __restrict__ x) {
    const int y0 = blockIdx.x, n = blockIdx.y;
    const int tid = threadIdx.x;
    __nv_bfloat16* oh = g_xpad_hi + (size_t)(n * XP + y0) * XP * CIN;
    __nv_bfloat16* ol = g_xpad_lo + (size_t)(n * XP + y0) * XP * CIN;

    if (y0 == 64) {
        for (int idx = tid; idx < XP * CIN / 8; idx += 256) {
            *(uint4*)(oh + idx * 8) = make_uint4(0, 0, 0, 0);
            *(uint4*)(ol + idx * 8) = make_uint4(0, 0, 0, 0);
        }
        return;
    }
    __shared__ float tile[64][65];
    for (int cc = 0; cc < 4; cc++) {
        #pragma unroll
        for (int r = 0; r < 16; r++) {
            int ci = (tid >> 6) + r * 4;
            int x0 = tid & 63;
            tile[ci][x0] = x[((size_t)(n * CIN + cc * 64 + ci) * HIN + y0) * WIN + x0];
        }
        __syncthreads();
        #pragma unroll
        for (int r = 0; r < 16; r++) {
            int x0 = (tid >> 6) + r * 4;
            int ci = tid & 63;
            float v = tile[ci][x0];
            __nv_bfloat16 h = __float2bfloat16(v);
            oh[x0 * CIN + cc * 64 + ci] = h;
            ol[x0 * CIN + cc * 64 + ci] = __float2bfloat16(v - __bfloat162float(h));
        }
        __syncthreads();
    }
    if (tid < CIN) {
        oh[64 * CIN + tid] = __float2bfloat16(0.f);
        ol[64 * CIN + tid] = __float2bfloat16(0.f);
    }
}

// ---------------------------------------------------------------------------
// Kernel 3: offset branch, warp-parallel
// ---------------------------------------------------------------------------
__global__ void __launch_bounds__(1024)
offsets_kernel(const float* __restrict__ lat,
               const float* __restrict__ w1,
               const float* __restrict__ b1,
               const float* __restrict__ w2,
               const float* __restrict__ b2) {
    __shared__ float h[NB][64];
    __shared__ float oc[NB][18];
    const int tid = threadIdx.x, lane = tid & 31, w = tid >> 5;

    #pragma unroll
    for (int t = 0; t < 4; t++) {
        int o = w * 4 + t;
        int n = o >> 6, j = o & 63;
        float s = 0.f;
        #pragma unroll
        for (int r = 0; r < 4; r++) {
            int i = lane + r * 32;
            s += lat[n * COUT + i] * w1[(j * COUT + i) * KK + 4];
        }
        #pragma unroll
        for (int d = 16; d; d >>= 1) s += __shfl_xor_sync(0xffffffffu, s, d);
        if (lane == 0) h[n][j] = fmaxf(s + b1[j], 0.f);
    }
    __syncthreads();

    for (int o = w; o < NB * 18; o += 32) {
        int n = o / 18, c = o % 18;
        float s = 0.f;
        #pragma unroll
        for (int r = 0; r < 2; r++) {
            int k = lane + r * 32;
            s += h[n][k] * w2[(c * 64 + k) * KK + 4];
        }
        #pragma unroll
        for (int d = 16; d; d >>= 1) s += __shfl_xor_sync(0xffffffffu, s, d);
        if (lane == 0) oc[n][c] = tanhf(s + b2[c]);
    }
    __syncthreads();

    if (tid < NB * KK) {
        int n = tid / KK, kk = tid % KK;
        float oy = oc[n][2 * kk], ox = oc[n][2 * kk + 1];
        float fy = floorf(oy), fx = floorf(ox);
        float dy = oy - fy,  dx = ox - fx;
        g_sy[n][kk] = (kk / 3 - 1) + (int)fy;
        g_sx[n][kk] = (kk % 3 - 1) + (int)fx;
        g_cw[n][kk][0] = (1.f - dy) * (1.f - dx);
        g_cw[n][kk][1] = (1.f - dy) * dx;
        g_cw[n][kk][2] = dy * (1.f - dx);
        g_cw[n][kk][3] = dy * dx;
    }
}

// ---------------------------------------------------------------------------
// Kernel 4: transposed conv as per-parity-class HMMA GEMM; 2 CTAs/SM.
// ---------------------------------------------------------------------------
__global__ void __launch_bounds__(256, 2)
tconv_gemm_kernel() {
    extern __shared__ __align__(16) unsigned char smraw[];
    const int Y   = blockIdx.x;
    const int pxp = blockIdx.y;
    const int n   = blockIdx.z;
    const int tid = threadIdx.x;
    const int lane = tid & 31, warp = tid >> 5;
    const int wm = warp & 1, wn = warp >> 1;

    const int py  = Y & 1;
    const int cls = py * 2 + pxp;
    const int Kc  = c_clsK[cls];
    const int kbase = c_clsBase[cls];
    const int nkx = pxp ? 2 : 1;
    const int stages = Kc >> 5;
    const int y0b = Y >> 1;
    const uint32_t smb = s2u(smraw);

    const __nv_bfloat16* Ah_src = g_Wch;
    const __nv_bfloat16* Al_src = g_Wcl;
    const __nv_bfloat16* Bh_src = g_xpad_hi + (size_t)n * XP * XP * CIN;
    const __nv_bfloat16* Bl_src = g_xpad_lo + (size_t)n * XP * XP * CIN;

    float acc[4][2][4];
    #pragma unroll
    for (int i = 0; i < 4; i++)
        #pragma unroll
        for (int j = 0; j < 2; j++)
            #pragma unroll
            for (int e = 0; e < 4; e++) acc[i][j][e] = 0.f;

    auto issue = [&](int s, int buf) {
        const int k0 = s * 32;
        const int tap = k0 >> 8;
        const int a = tap / nkx, b = tap % nkx;
        const int yy = y0b + (py ? a : 0);
        const int d  = pxp ? b : 0;
        const int cib = k0 & 255;
        const size_t brow = ((size_t)yy * XP) * CIN;
        #pragma unroll
        for (int j = 0; j < 6; j++) {
            int id = tid + j * 256;
            uint32_t base = smb + buf * 30720;
            if (id < 1024) {
                int t = id >> 9;
                int rid = id & 511;
                int r = rid >> 2, c = rid & 3;
                uint32_t dst = base + t * 10240 + r * 80 + c * 16;
                const __nv_bfloat16* src = (t ? Al_src : Ah_src)
                    + (size_t)r * 2304 + kbase + k0 + c * 8;
                cp16(dst, src);
            } else {
                int rid = id - 1024;
                int t = rid >> 8;
                int rr = rid & 255;
                int r = rr >> 2, c = rr & 3;
                uint32_t dst = base + 20480 + t * 5120 + r * 80 + c * 16;
                const __nv_bfloat16* src = (t ? Bl_src : Bh_src)
                    + brow + (size_t)(r + d) * CIN + cib + c * 8;
                cp16(dst, src);
            }
        }
        cp_commit();
    };

    issue(0, 0);

    for (int s = 0; s < stages; s++) {
        cp_wait_all();
        __syncthreads();
        if (s + 1 < stages) issue(s + 1, (s + 1) & 1);

        const int buf = s & 1;
        const uint32_t Ab = smb + buf * 30720;
        const uint32_t Bb = Ab + 20480;

        #pragma unroll
        for (int ks = 0; ks < 2; ks++) {
            uint32_t afr[2][4][4];
            #pragma unroll
            for (int t = 0; t < 2; t++)
                #pragma unroll
                for (int mt = 0; mt < 4; mt++) {
                    uint32_t ad = Ab + t * 10240 +
                        (wm * 64 + mt * 16 + (lane & 15)) * 80 + ks * 32 + (lane >> 4) * 16;
                    ldsm4(afr[t][mt], ad);
                }
            uint32_t bfr[2][2][2];
            #pragma unroll
            for (int t = 0; t < 2; t++)
                #pragma unroll
                for (int nt = 0; nt < 2; nt++) {
                    uint32_t bd = Bb + t * 5120 +
                        (wn * 16 + nt * 8 + (lane & 7)) * 80 + ks * 32 + ((lane >> 3) & 1) * 16;
                    ldsm2(bfr[t][nt], bd);
                }
            #pragma unroll
            for (int mt = 0; mt < 4; mt++)
                #pragma unroll
                for (int nt = 0; nt < 2; nt++) {
                    mma_bf16(acc[mt][nt], afr[0][mt], bfr[0][nt]);
                    mma_bf16(acc[mt][nt], afr[0][mt], bfr[1][nt]);
                    mma_bf16(acc[mt][nt], afr[1][mt], bfr[0][nt]);
                }
        }
        __syncthreads();
    }

    float* up = g_upcl + (size_t)(n * HH + Y) * WW * COUT;
    #pragma unroll
    for (int mt = 0; mt < 4; mt++) {
        int m0 = wm * 64 + mt * 16 + (lane >> 2);
        #pragma unroll
        for (int nt = 0; nt < 2; nt++) {
            int px0 = wn * 16 + nt * 8 + (lane & 3) * 2;
            up[(size_t)(2 * px0 + pxp) * COUT + m0]           = acc[mt][nt][0];
            up[(size_t)(2 * (px0 + 1) + pxp) * COUT + m0]     = acc[mt][nt][1];
            up[(size_t)(2 * px0 + pxp) * COUT + m0 + 8]       = acc[mt][nt][2];
            up[(size_t)(2 * (px0 + 1) + pxp) * COUT + m0 + 8] = acc[mt][nt][3];
        }
    }
}

// ---------------------------------------------------------------------------
// Kernel 5: bilinear sampler -> S[n][px][kk*128+ci] bf16 hi/lo.
// ---------------------------------------------------------------------------
__global__ void __launch_bounds__(256)
sample_kernel() {
    const int kk = blockIdx.x, y = blockIdx.y, n = blockIdx.z;
    const int lane = threadIdx.x & 31, w = threadIdx.x >> 5;
    const int sy = g_sy[n][kk], sx = g_sx[n][kk];
    const float c00 = g_cw[n][kk][0], c01 = g_cw[n][kk][1];
    const float c10 = g_cw[n][kk][2], c11 = g_cw[n][kk][3];
    const float* base = g_upcl + (size_t)n * HH * WW * COUT;
    const int y0 = y + sy;
    const bool yA = (unsigned)y0 < HH, yB = (unsigned)(y0 + 1) < HH;

    for (int x = w; x < WW; x += 8) {
        const int x0 = x + sx;
        const bool xA = (unsigned)x0 < WW, xB = (unsigned)(x0 + 1) < WW;
        float4 v = make_float4(0.f, 0.f, 0.f, 0.f);
        const float* r00 = base + ((size_t)y0 * WW + x0) * COUT + lane * 4;
        if (yA & xA) {
            float4 t = *(const float4*)r00;
            v.x += c00 * t.x; v.y += c00 * t.y; v.z += c00 * t.z; v.w += c00 * t.w;
        }
        if (yA & xB) {
            float4 t = *(const float4*)(r00 + COUT);
            v.x += c01 * t.x; v.y += c01 * t.y; v.z += c01 * t.z; v.w += c01 * t.w;
        }
        if (yB & xA) {
            float4 t = *(const float4*)(r00 + WW * COUT);
            v.x += c10 * t.x; v.y += c10 * t.y; v.z += c10 * t.z; v.w += c10 * t.w;
        }
        if (yB & xB) {
            float4 t = *(const float4*)(r00 + WW * COUT + COUT);
            v.x += c11 * t.x; v.y += c11 * t.y; v.z += c11 * t.z; v.w += c11 * t.w;
        }
        BFP ph, pl;
        float vv[4] = {v.x, v.y, v.z, v.w};
        #pragma unroll
        for (int e = 0; e < 4; e++) {
            __nv_bfloat16 hb = __float2bfloat16(vv[e]);
            ph.b[e] = hb;
            pl.b[e] = __float2bfloat16(vv[e] - __bfloat162float(hb));
        }
        size_t so = ((size_t)((n * HH + y) * WW + x)) * KTOT + kk * COUT + lane * 4;
        *(uint2*)(g_Shi + so) = ph.v;
        *(uint2*)(g_Slo + so) = pl.v;
    }
}

// ---------------------------------------------------------------------------
// Kernel 6: deform GEMM, ob-merged: M=256 x N=128 per CTA (16 warps),
// 3-stage cp.async ring. Grid (y=128, n=2).
// smem/stage: Ah 20480 | Al 20480 | Bh 10240 | Bl 10240 = 61440; x3 = 184320.
// ---------------------------------------------------------------------------
__global__ void __launch_bounds__(512, 1)
gemm_kernel(float* __restrict__ out) {
    extern __shared__ __align__(16) unsigned char smraw[];
    const int y   = blockIdx.x;
    const int n   = blockIdx.y;
    const int tid = threadIdx.x;
    const int lane = tid & 31, warp = tid >> 5;
    const int wm = warp & 3, wn = warp >> 2;   // 4x4 warp grid: 64 M x 32 N each

    const uint32_t smb = s2u(smraw);

    const __nv_bfloat16* srcA_h = g_Whi;
    const __nv_bfloat16* srcA_l = g_Wlo;
    const size_t bofs = (size_t)((n * HH + y) * WW) * KTOT;
    const __nv_bfloat16* srcB_h = g_Shi + bofs;
    const __nv_bfloat16* srcB_l = g_Slo + bofs;

    float acc[4][4][4];
    #pragma unroll
    for (int i = 0; i < 4; i++)
        #pragma unroll
        for (int j = 0; j < 4; j++)
            #pragma unroll
            for (int e = 0; e < 4; e++) acc[i][j][e] = 0.f;

    auto issue = [&](int s, int buf) {
        const int k0 = s * 32;
        #pragma unroll
        for (int j = 0; j < 6; j++) {
            int chunk = tid + j * 512;          // 0..3071
            uint32_t base = smb + buf * 61440;
            if (chunk < 2048) {                 // A tiles: 2 x 256 rows x 4 chunks
                int t = chunk >> 10;
                int rid = chunk & 1023;
                int r = rid >> 2, c = rid & 3;
                uint32_t dst = base + t * 20480 + r * 80 + c * 16;
                const __nv_bfloat16* src = (t ? srcA_l : srcA_h) + (size_t)r * KTOT + k0 + c * 8;
                cp16(dst, src);
            } else {                            // B tiles: 2 x 128 rows x 4 chunks
                int rid = chunk - 2048;
                int t = rid >> 9;
                int rr = rid & 511;
                int r = rr >> 2, c = rr & 3;
                uint32_t dst = base + 40960 + t * 10240 + r * 80 + c * 16;
                const __nv_bfloat16* src = (t ? srcB_l : srcB_h) + (size_t)r * KTOT + k0 + c * 8;
                cp16(dst, src);
            }
        }
        cp_commit();
    };

    issue(0, 0);
    issue(1, 1);

    for (int s = 0; s < STAGES; s++) {
        cp_wait_1();            // stage s copy complete (<=1 group pending)
        __syncthreads();        // all warps done with the buffer being refilled
        if (s + 2 < STAGES) issue(s + 2, (s + 2) % 3);

        const int buf = s % 3;
        const uint32_t Ab = smb + buf * 61440;
        const uint32_t Bb = Ab + 40960;

        #pragma unroll
        for (int ks = 0; ks < 2; ks++) {
            uint32_t afr[2][4][4];
            #pragma unroll
            for (int t = 0; t < 2; t++)
                #pragma unroll
                for (int mt = 0; mt < 4; mt++) {
                    uint32_t ad = Ab + t * 20480 +
                        (wm * 64 + mt * 16 + (lane & 15)) * 80 + ks * 32 + (lane >> 4) * 16;
                    ldsm4(afr[t][mt], ad);
                }
            uint32_t bfr[2][4][2];
            #pragma unroll
            for (int t = 0; t < 2; t++)
                #pragma unroll
                for (int nt = 0; nt < 4; nt++) {
                    uint32_t bd = Bb + t * 10240 +
                        (wn * 32 + nt * 8 + (lane & 7)) * 80 + ks * 32 + ((lane >> 3) & 1) * 16;
                    ldsm2(bfr[t][nt], bd);
                }
            #pragma unroll
            for (int mt = 0; mt < 4; mt++)
                #pragma unroll
                for (int nt = 0; nt < 4; nt++) {
                    mma_bf16(acc[mt][nt], afr[0][mt], bfr[0][nt]);
                    mma_bf16(acc[mt][nt], afr[0][mt], bfr[1][nt]);
                    mma_bf16(acc[mt][nt], afr[1][mt], bfr[0][nt]);
                }
        }
    }

    #pragma unroll
    for (int mt = 0; mt < 4; mt++) {
        int m = wm * 64 + mt * 16 + (lane >> 2);
        float* pbase = out + (((size_t)(n * CIN + m) * HH + y) * WW);
        #pragma unroll
        for (int nt = 0; nt < 4; nt++) {
            int xcol = wn * 32 + nt * 8 + (lane & 3) * 2;
            *(float2*)(pbase + xcol) = make_float2(acc[mt][nt][0], acc[mt][nt][1]);
            *(float2*)(pbase + 8 * HH * WW + xcol) = make_float2(acc[mt][nt][2], acc[mt][nt][3]);
        }
    }
}

// ---------------------------------------------------------------------------
extern "C" void kernel_launch(void* const* d_in, const int* in_sizes, int n_in,
                              void* d_out, int out_size) {
    const float* x   = (const float*)d_in[0];
    const float* lat = (const float*)d_in[1];
    const float* tw  = (const float*)d_in[2];
    const float* w1  = (const float*)d_in[3];
    const float* b1  = (const float*)d_in[4];
    const float* w2  = (const float*)d_in[5];
    const float* b2  = (const float*)d_in[6];
    float* out = (float*)d_out;

    cudaFuncSetAttribute(gemm_kernel,
                         cudaFuncAttributeMaxDynamicSharedMemorySize, 184320);
    cudaFuncSetAttribute(tconv_gemm_kernel,
                         cudaFuncAttributeMaxDynamicSharedMemorySize, 61440);

    wprep_kernel<<<(CIN * KTOT + 255) / 256, 256>>>(tw);
    xsplit_kernel<<<dim3(XP, NB), 256>>>(x);
    offsets_kernel<<<1, 1024>>>(lat, w1, b1, w2, b2);
    {
        dim3 grid(HH, 2, NB);
        tconv_gemm_kernel<<<grid, 256, 61440>>>();
    }
    {
        dim3 grid(KK, HH, NB);
        sample_kernel<<<grid, 256>>>();
    }
    {
        dim3 grid(HH, NB);
        gemm_kernel<<<grid, 512, 184320>>>(out);
    }
}